// round 2
// baseline (speedup 1.0000x reference)
#include <cuda_runtime.h>
#include <math.h>

#define Bb 4
#define Nn 4096
#define KK 16
#define DP 64
#define DM 128
#define BN (Bb*Nn)
#define EPSV 1e-8f
#define TS 8
#define SAT_STRIDE 132

// ---------------- scratch (no allocations allowed) ----------------
__device__ float g_x[BN*DM];
__device__ float g_q[BN*DM];
__device__ float g_k[BN*DM];
__device__ float g_v[BN*DM];
__device__ float g_qn[BN];
__device__ int   g_knn[BN*KK];
__device__ float g_ve[BN*KK*DM];   // v + pos_enc
__device__ float g_r[BN*DM];

// ---------------- KNN: exact reference arithmetic, stable top-16 ----------------
__global__ void knn_kernel(const float* __restrict__ xyz) {
    extern __shared__ float sm[];
    float* sx = sm;
    float* sy = sm + Nn;
    float* sz = sm + 2*Nn;
    float* ssq = sm + 3*Nn;
    const int b = blockIdx.y;
    const float* base = xyz + (size_t)b*Nn*3;
    for (int m = threadIdx.x; m < Nn; m += blockDim.x) {
        float x = base[m*3+0], y = base[m*3+1], z = base[m*3+2];
        sx[m] = x; sy[m] = y; sz[m] = z;
        float s = __fadd_rn(__fadd_rn(__fmul_rn(x,x), __fmul_rn(y,y)), __fmul_rn(z,z));
        ssq[m] = s;
    }
    __syncthreads();
    const int q = blockIdx.x*blockDim.x + threadIdx.x;
    const float qx = sx[q], qy = sy[q], qz = sz[q], qs = ssq[q];
    float bd[KK]; int bi[KK];
    #pragma unroll
    for (int i=0;i<KK;i++){ bd[i]=3.4e38f; bi[i]=Nn; }
    for (int m=0;m<Nn;m++) {
        float dot = __fmul_rn(qx, sx[m]);
        dot = __fadd_rn(dot, __fmul_rn(qy, sy[m]));
        dot = __fadd_rn(dot, __fmul_rn(qz, sz[m]));
        float d = __fsub_rn(__fadd_rn(qs, ssq[m]), __fmul_rn(2.0f, dot));
        if (d < bd[KK-1]) {
            int j = KK-1;
            while (j > 0 && d < bd[j-1]) { bd[j]=bd[j-1]; bi[j]=bi[j-1]; j--; }
            bd[j]=d; bi[j]=m;
        }
    }
    int* o = g_knn + ((size_t)(b*Nn + q))*KK;
    #pragma unroll
    for (int i=0;i<KK;i++) o[i] = bi[i];
}

// ---------------- x = features @ fc1_w + fc1_b ----------------
__global__ void fc1_kernel(const float* __restrict__ feat,
                           const float* __restrict__ w,
                           const float* __restrict__ bias) {
    int gid = blockIdx.x*blockDim.x + threadIdx.x;      // BN*DM threads
    int row = gid >> 7, c = gid & 127;
    const float* f = feat + (size_t)row*DP;
    float a = 0.f;
    #pragma unroll 8
    for (int d=0; d<DP; d++) a = fmaf(f[d], w[d*DM + c], a);
    g_x[gid] = a + bias[c];
}

// ---------------- q,k,v projections ----------------
__global__ void qkv_kernel(const float* __restrict__ wq,
                           const float* __restrict__ wk,
                           const float* __restrict__ wv) {
    int gid = blockIdx.x*blockDim.x + threadIdx.x;      // BN*DM threads
    int row = gid >> 7, c = gid & 127;
    const float* x = g_x + (size_t)row*DM;
    float aq=0.f, ak=0.f, av=0.f;
    #pragma unroll 4
    for (int d=0; d<DM; d++) {
        float xv = x[d];
        aq = fmaf(xv, wq[d*DM + c], aq);
        ak = fmaf(xv, wk[d*DM + c], ak);
        av = fmaf(xv, wv[d*DM + c], av);
    }
    g_q[gid]=aq; g_k[gid]=ak; g_v[gid]=av;
}

// ---------------- per-row q norm ----------------
__global__ void qn_kernel() {
    int w = (blockIdx.x*blockDim.x + threadIdx.x) >> 5; // one warp per row
    int lane = threadIdx.x & 31;
    const float* q = g_q + (size_t)w*DM;
    float s = 0.f;
    #pragma unroll
    for (int i=lane; i<DM; i+=32) { float v=q[i]; s = fmaf(v,v,s); }
    #pragma unroll
    for (int o=16;o;o>>=1) s += __shfl_xor_sync(0xffffffffu, s, o);
    if (lane==0) g_qn[w] = fmaxf(sqrtf(s), EPSV);
}

// ---------------- fused attention-MLP tile kernel ----------------
__device__ __forceinline__ void gemm_tile(const float* __restrict__ sAT,
                                          const float* __restrict__ sW,
                                          float acc[8][8], int ty, int tx) {
    #pragma unroll 2
    for (int kk=0; kk<DM; kk++) {
        const float4 a0 = *reinterpret_cast<const float4*>(sAT + kk*SAT_STRIDE + ty*8);
        const float4 a1 = *reinterpret_cast<const float4*>(sAT + kk*SAT_STRIDE + ty*8 + 4);
        const float4 b0 = *reinterpret_cast<const float4*>(sW + kk*DM + tx*8);
        const float4 b1 = *reinterpret_cast<const float4*>(sW + kk*DM + tx*8 + 4);
        float av[8] = {a0.x,a0.y,a0.z,a0.w,a1.x,a1.y,a1.z,a1.w};
        float bv[8] = {b0.x,b0.y,b0.z,b0.w,b1.x,b1.y,b1.z,b1.w};
        #pragma unroll
        for (int i=0;i<8;i++)
            #pragma unroll
            for (int j=0;j<8;j++)
                acc[i][j] = fmaf(av[i], bv[j], acc[i][j]);
    }
}

__global__ void __launch_bounds__(256,1) attn_kernel(
    const float* __restrict__ xyz,
    const float* __restrict__ d1_w, const float* __restrict__ d1_b,
    const float* __restrict__ d2_w, const float* __restrict__ d2_b,
    const float* __restrict__ sim_w, const float* __restrict__ sim_b,
    const float* __restrict__ g1_w, const float* __restrict__ g1_b,
    const float* __restrict__ g2_w, const float* __restrict__ g2_b,
    float* __restrict__ attn_out)
{
    extern __shared__ float smf[];
    float* sAT  = smf;                          // [128][132] transposed input
    float* sW   = sAT + DM*SAT_STRIDE;          // [128][128] weights
    float* sPE  = sW + DM*DM;                   // [128][128] pos_enc
    float* sSim = sPE + DM*DM;                  // [128]
    float* sKKd = sSim + 128;                   // [128] k·k dots
    float* sKxyz = sKKd + 128;                  // [128*3]
    float* sQxyz = sKxyz + 384;                 // [8*3]
    __shared__ int sIdx[128];

    const int t = threadIdx.x;
    const int ty = t >> 4, tx = t & 15;
    const int tile = blockIdx.x;                // 2048 tiles
    const int b = tile >> 9;                    // 512 tiles per batch
    const int n0 = (tile & 511) * TS;
    const int bn0 = b*Nn + n0;

    if (t < 128) {
        int id = g_knn[(size_t)bn0*KK + t];
        sIdx[t] = id;
        const float* p = xyz + (size_t)(b*Nn + id)*3;
        sKxyz[t*3+0]=p[0]; sKxyz[t*3+1]=p[1]; sKxyz[t*3+2]=p[2];
    } else if (t < 136) {
        int r = t - 128;
        const float* p = xyz + (size_t)(bn0 + r)*3;
        sQxyz[r*3+0]=p[0]; sQxyz[r*3+1]=p[1]; sQxyz[r*3+2]=p[2];
    }
    __syncthreads();

    // ---- stage A: h1 = relu(rel_pos @ d1 + b1) -> sAT ; stage weights d2_w -> sW
    #pragma unroll 4
    for (int i=0;i<64;i++) {
        int e = i*256 + t;
        int ch = e >> 7, pr = e & 127;
        int r = pr >> 4;
        float rx = sQxyz[r*3+0]-sKxyz[pr*3+0];
        float ry = sQxyz[r*3+1]-sKxyz[pr*3+1];
        float rz = sQxyz[r*3+2]-sKxyz[pr*3+2];
        float h = d1_b[ch];
        h = fmaf(rx, d1_w[ch], h);
        h = fmaf(ry, d1_w[DM+ch], h);
        h = fmaf(rz, d1_w[2*DM+ch], h);
        sAT[ch*SAT_STRIDE + pr] = fmaxf(h, 0.f);
    }
    for (int i = t*4; i < DM*DM; i += 1024)
        *(float4*)(sW+i) = *(const float4*)(d2_w+i);
    __syncthreads();

    float acc[8][8];
    // ---- GEMM1: pos_enc = h1 @ d2_w
    #pragma unroll
    for (int i=0;i<8;i++)
        #pragma unroll
        for (int j=0;j<8;j++) acc[i][j]=0.f;
    gemm_tile(sAT, sW, acc, ty, tx);

    // epilogue 1: pos_enc -> sPE ; ve = v_gather + pos_enc -> global
    #pragma unroll
    for (int i=0;i<8;i++) {
        int row = ty*8+i;
        float pv[8];
        #pragma unroll
        for (int j=0;j<8;j++) {
            pv[j] = acc[i][j] + d2_b[tx*8+j];
            sPE[row*DM + tx*8 + j] = pv[j];
        }
        const float* vp = g_v + (size_t)(b*Nn + sIdx[row])*DM + tx*8;
        float* vep = g_ve + ((size_t)(bn0*KK + row))*DM + tx*8;
        float4 va = *(const float4*)vp;
        float4 vb = *(const float4*)(vp+4);
        float4 oa = make_float4(va.x+pv[0], va.y+pv[1], va.z+pv[2], va.w+pv[3]);
        float4 ob = make_float4(vb.x+pv[4], vb.y+pv[5], vb.z+pv[6], vb.w+pv[7]);
        *(float4*)vep = oa; *(float4*)(vep+4) = ob;
    }
    __syncthreads();

    // ---- stage C: dots, q-k -> sAT, sim_w rows 1.. -> sW
    float qkdot = 0.f;
    if (t < 128) {
        const float4* qp = (const float4*)(g_q + (size_t)(bn0 + (t>>4))*DM);
        const float4* kp = (const float4*)(g_k + (size_t)(b*Nn + sIdx[t])*DM);
        #pragma unroll 8
        for (int c=0;c<32;c++) {
            float4 a = qp[c], k4 = kp[c];
            qkdot = fmaf(a.x,k4.x,qkdot); qkdot = fmaf(a.y,k4.y,qkdot);
            qkdot = fmaf(a.z,k4.z,qkdot); qkdot = fmaf(a.w,k4.w,qkdot);
        }
    } else {
        int p = t-128;
        const float4* kp = (const float4*)(g_k + (size_t)(b*Nn + sIdx[p])*DM);
        float s = 0.f;
        #pragma unroll 8
        for (int c=0;c<32;c++) {
            float4 k4 = kp[c];
            s = fmaf(k4.x,k4.x,s); s = fmaf(k4.y,k4.y,s);
            s = fmaf(k4.z,k4.z,s); s = fmaf(k4.w,k4.w,s);
        }
        sKKd[p] = s;
    }
    #pragma unroll 4
    for (int i=0;i<64;i++) {
        int e = i*256 + t;
        int ch = e >> 7, pr = e & 127;
        float qv = g_q[(size_t)(bn0 + (pr>>4))*DM + ch];
        float kv = g_k[(size_t)(b*Nn + sIdx[pr])*DM + ch];
        sAT[ch*SAT_STRIDE + pr] = qv - kv;
    }
    for (int i = t*4; i < DM*DM; i += 1024)
        *(float4*)(sW+i) = *(const float4*)(sim_w + DM + i);
    __syncthreads();
    if (t < 128) {
        float kn = fmaxf(sqrtf(sKKd[t]), EPSV);
        float qn = g_qn[bn0 + (t>>4)];
        sSim[t] = qkdot / (qn * kn);
    }
    __syncthreads();

    // ---- GEMM2: (q-k) @ sim_w[1:]
    #pragma unroll
    for (int i=0;i<8;i++)
        #pragma unroll
        for (int j=0;j<8;j++) acc[i][j]=0.f;
    gemm_tile(sAT, sW, acc, ty, tx);
    __syncthreads();

    // epilogue 2: t = rel_qk + pos_enc -> sAT (transposed) ; g1_w -> sW
    #pragma unroll
    for (int i=0;i<8;i++) {
        int row = ty*8+i;
        float sv = sSim[row];
        #pragma unroll
        for (int j=0;j<8;j++) {
            int col = tx*8+j;
            float tv = acc[i][j] + sv*sim_w[col] + sim_b[col] + sPE[row*DM + col];
            sAT[col*SAT_STRIDE + row] = tv;
        }
    }
    for (int i = t*4; i < DM*DM; i += 1024)
        *(float4*)(sW+i) = *(const float4*)(g1_w+i);
    __syncthreads();

    // ---- GEMM3: a1 = relu(t @ g1 + b)
    #pragma unroll
    for (int i=0;i<8;i++)
        #pragma unroll
        for (int j=0;j<8;j++) acc[i][j]=0.f;
    gemm_tile(sAT, sW, acc, ty, tx);
    __syncthreads();

    #pragma unroll
    for (int i=0;i<8;i++) {
        int row = ty*8+i;
        #pragma unroll
        for (int j=0;j<8;j++) {
            int col = tx*8+j;
            sAT[col*SAT_STRIDE + row] = fmaxf(acc[i][j] + g1_b[col], 0.f);
        }
    }
    for (int i = t*4; i < DM*DM; i += 1024)
        *(float4*)(sW+i) = *(const float4*)(g2_w+i);
    __syncthreads();

    // ---- GEMM4: attn_pre = a1 @ g2 + b -> d_out attn region
    #pragma unroll
    for (int i=0;i<8;i++)
        #pragma unroll
        for (int j=0;j<8;j++) acc[i][j]=0.f;
    gemm_tile(sAT, sW, acc, ty, tx);

    #pragma unroll
    for (int i=0;i<8;i++) {
        int row = ty*8+i;
        float* op = attn_out + ((size_t)(bn0*KK + row))*DM + tx*8;
        float o[8];
        #pragma unroll
        for (int j=0;j<8;j++) o[j] = acc[i][j] + g2_b[tx*8+j];
        *(float4*)op     = make_float4(o[0],o[1],o[2],o[3]);
        *(float4*)(op+4) = make_float4(o[4],o[5],o[6],o[7]);
    }
}

// ---------------- softmax over K axis + weighted reduce ----------------
__global__ void softmax_kernel(float* __restrict__ attn) {
    int gid = blockIdx.x*blockDim.x + threadIdx.x;   // BN*DM threads
    int bn = gid >> 7, ch = gid & 127;
    size_t base = (size_t)bn*KK*DM + ch;
    const float sc = 0.08838834764831843f;           // 1/sqrt(128)
    float v[KK];
    float m = -3.4e38f;
    #pragma unroll
    for (int k=0;k<KK;k++){ v[k] = attn[base + k*DM]*sc; m = fmaxf(m, v[k]); }
    float s = 0.f;
    #pragma unroll
    for (int k=0;k<KK;k++){ v[k] = expf(v[k]-m); s += v[k]; }
    float inv = 1.0f/s;
    float r = 0.f;
    #pragma unroll
    for (int k=0;k<KK;k++){
        float a = v[k]*inv;
        attn[base + k*DM] = a;
        r = fmaf(a, g_ve[base + k*DM], r);
    }
    g_r[gid] = r;
}

// ---------------- res = r @ fc2 + b + features ----------------
__global__ void out_kernel(const float* __restrict__ fc2_w, const float* __restrict__ fc2_b,
                           const float* __restrict__ feat, float* __restrict__ res) {
    int gid = blockIdx.x*blockDim.x + threadIdx.x;   // BN*DP threads
    int bn = gid >> 6, c = gid & 63;
    const float* r = g_r + (size_t)bn*DM;
    float a = 0.f;
    #pragma unroll 8
    for (int d=0; d<DM; d++) a = fmaf(r[d], fc2_w[d*DP + c], a);
    res[gid] = a + fc2_b[c] + feat[gid];
}

// ---------------- launch ----------------
extern "C" void kernel_launch(void* const* d_in, const int* in_sizes, int n_in,
                              void* d_out, int out_size) {
    const float* xyz      = (const float*)d_in[0];
    const float* features = (const float*)d_in[1];
    const float* fc1_w = (const float*)d_in[2];
    const float* fc1_b = (const float*)d_in[3];
    const float* fc2_w = (const float*)d_in[4];
    const float* fc2_b = (const float*)d_in[5];
    const float* d1_w  = (const float*)d_in[6];
    const float* d1_b  = (const float*)d_in[7];
    const float* d2_w  = (const float*)d_in[8];
    const float* d2_b  = (const float*)d_in[9];
    const float* g1_w  = (const float*)d_in[10];
    const float* g1_b  = (const float*)d_in[11];
    const float* g2_w  = (const float*)d_in[12];
    const float* g2_b  = (const float*)d_in[13];
    const float* wq_w  = (const float*)d_in[14];
    const float* wk_w  = (const float*)d_in[15];
    const float* wv_w  = (const float*)d_in[16];
    const float* sim_w = (const float*)d_in[17];
    const float* sim_b = (const float*)d_in[18];

    float* res  = (float*)d_out;                       // (B,N,DP)
    float* attn = res + (size_t)BN*DP;                 // (B,N,K,DM)

    const int KNN_SMEM  = 4*Nn*(int)sizeof(float);     // 64 KB
    const int ATTN_SMEM = (DM*SAT_STRIDE + 2*DM*DM + 128 + 128 + 384 + 24)
                          * (int)sizeof(float);        // ~197 KB
    static int attr_done = 0;
    if (!attr_done) {
        cudaFuncSetAttribute(knn_kernel,  cudaFuncAttributeMaxDynamicSharedMemorySize, KNN_SMEM);
        cudaFuncSetAttribute(attn_kernel, cudaFuncAttributeMaxDynamicSharedMemorySize, ATTN_SMEM);
        attr_done = 1;
    }

    knn_kernel<<<dim3(Nn/256, Bb), 256, KNN_SMEM>>>(xyz);
    fc1_kernel<<<(BN*DM)/256, 256>>>(features, fc1_w, fc1_b);
    qkv_kernel<<<(BN*DM)/256, 256>>>(wq_w, wk_w, wv_w);
    qn_kernel<<<BN/8, 256>>>();
    attn_kernel<<<BN/TS, 256, ATTN_SMEM>>>(xyz, d1_w, d1_b, d2_w, d2_b,
                                           sim_w, sim_b, g1_w, g1_b, g2_w, g2_b, attn);
    softmax_kernel<<<(BN*DM)/256, 256>>>(attn);
    out_kernel<<<(BN*DP)/256, 256>>>(fc2_w, fc2_b, features, res);
}

// round 3
// speedup vs baseline: 1.0241x; 1.0241x over previous
#include <cuda_runtime.h>
#include <math.h>

#define Bb 4
#define Nn 4096
#define KK 16
#define DP 64
#define DM 128
#define BN (Bb*Nn)
#define EPSV 1e-8f
#define TS 8
#define SAT_STRIDE 132

// ---------------- scratch (no allocations allowed) ----------------
__device__ float g_x[BN*DM];
__device__ float g_q[BN*DM];
__device__ float g_k[BN*DM];
__device__ float g_v[BN*DM];
__device__ float g_qn[BN];
__device__ int   g_knn[BN*KK];
__device__ float g_ve[BN*KK*DM];   // v + pos_enc
__device__ float g_r[BN*DM];

// ---------------- packed f32x2 helpers ----------------
__device__ __forceinline__ float2 unpk(unsigned long long v) {
    float2 r;
    asm("mov.b64 {%0, %1}, %2;" : "=f"(r.x), "=f"(r.y) : "l"(v));
    return r;
}

// ---------------- KNN: exact reference arithmetic, stable top-16 ----------------
__global__ void knn_kernel(const float* __restrict__ xyz) {
    extern __shared__ float sm[];
    float* sx = sm;
    float* sy = sm + Nn;
    float* sz = sm + 2*Nn;
    float* ssq = sm + 3*Nn;
    const int b = blockIdx.y;
    const float* base = xyz + (size_t)b*Nn*3;
    for (int m = threadIdx.x; m < Nn; m += blockDim.x) {
        float x = base[m*3+0], y = base[m*3+1], z = base[m*3+2];
        sx[m] = x; sy[m] = y; sz[m] = z;
        float s = __fadd_rn(__fadd_rn(__fmul_rn(x,x), __fmul_rn(y,y)), __fmul_rn(z,z));
        ssq[m] = s;
    }
    __syncthreads();
    const int q = blockIdx.x*blockDim.x + threadIdx.x;
    const float qx = sx[q], qy = sy[q], qz = sz[q], qs = ssq[q];
    float bd[KK]; int bi[KK];
    #pragma unroll
    for (int i=0;i<KK;i++){ bd[i]=3.4e38f; bi[i]=Nn; }
    for (int m=0;m<Nn;m++) {
        float dot = __fmul_rn(qx, sx[m]);
        dot = __fadd_rn(dot, __fmul_rn(qy, sy[m]));
        dot = __fadd_rn(dot, __fmul_rn(qz, sz[m]));
        float d = __fsub_rn(__fadd_rn(qs, ssq[m]), __fmul_rn(2.0f, dot));
        if (d < bd[KK-1]) {
            int j = KK-1;
            while (j > 0 && d < bd[j-1]) { bd[j]=bd[j-1]; bi[j]=bi[j-1]; j--; }
            bd[j]=d; bi[j]=m;
        }
    }
    int* o = g_knn + ((size_t)(b*Nn + q))*KK;
    #pragma unroll
    for (int i=0;i<KK;i++) o[i] = bi[i];
}

// ---------------- x = features @ fc1_w + fc1_b ----------------
__global__ void fc1_kernel(const float* __restrict__ feat,
                           const float* __restrict__ w,
                           const float* __restrict__ bias) {
    int gid = blockIdx.x*blockDim.x + threadIdx.x;      // BN*DM threads
    int row = gid >> 7, c = gid & 127;
    const float* f = feat + (size_t)row*DP;
    float a = 0.f;
    #pragma unroll 8
    for (int d=0; d<DP; d++) a = fmaf(f[d], w[d*DM + c], a);
    g_x[gid] = a + bias[c];
}

// ---------------- q,k,v projections ----------------
__global__ void qkv_kernel(const float* __restrict__ wq,
                           const float* __restrict__ wk,
                           const float* __restrict__ wv) {
    int gid = blockIdx.x*blockDim.x + threadIdx.x;      // BN*DM threads
    int row = gid >> 7, c = gid & 127;
    const float* x = g_x + (size_t)row*DM;
    float aq=0.f, ak=0.f, av=0.f;
    #pragma unroll 4
    for (int d=0; d<DM; d++) {
        float xv = x[d];
        aq = fmaf(xv, wq[d*DM + c], aq);
        ak = fmaf(xv, wk[d*DM + c], ak);
        av = fmaf(xv, wv[d*DM + c], av);
    }
    g_q[gid]=aq; g_k[gid]=ak; g_v[gid]=av;
}

// ---------------- per-row q norm ----------------
__global__ void qn_kernel() {
    int w = (blockIdx.x*blockDim.x + threadIdx.x) >> 5; // one warp per row
    int lane = threadIdx.x & 31;
    const float* q = g_q + (size_t)w*DM;
    float s = 0.f;
    #pragma unroll
    for (int i=lane; i<DM; i+=32) { float v=q[i]; s = fmaf(v,v,s); }
    #pragma unroll
    for (int o=16;o;o>>=1) s += __shfl_xor_sync(0xffffffffu, s, o);
    if (lane==0) g_qn[w] = fmaxf(sqrtf(s), EPSV);
}

// ---------------- packed-FMA GEMM micro-kernel (2 fp32 FMA per issue) ----------------
__device__ __forceinline__ void gemm_tile2(const float* __restrict__ sAT,
                                           const float* __restrict__ sW,
                                           unsigned long long acc[8][4], int ty, int tx) {
    #pragma unroll 4
    for (int kk=0; kk<DM; kk++) {
        const float4 a0 = *reinterpret_cast<const float4*>(sAT + kk*SAT_STRIDE + ty*8);
        const float4 a1 = *reinterpret_cast<const float4*>(sAT + kk*SAT_STRIDE + ty*8 + 4);
        const ulonglong2 b0 = *reinterpret_cast<const ulonglong2*>(sW + kk*DM + tx*8);
        const ulonglong2 b1 = *reinterpret_cast<const ulonglong2*>(sW + kk*DM + tx*8 + 4);
        unsigned long long bv[4] = {b0.x, b0.y, b1.x, b1.y};
        float av[8] = {a0.x,a0.y,a0.z,a0.w,a1.x,a1.y,a1.z,a1.w};
        #pragma unroll
        for (int i=0;i<8;i++) {
            unsigned long long aa;
            asm("mov.b64 %0, {%1, %1};" : "=l"(aa) : "f"(av[i]));
            #pragma unroll
            for (int j=0;j<4;j++)
                asm("fma.rn.f32x2 %0, %1, %2, %0;" : "+l"(acc[i][j]) : "l"(aa), "l"(bv[j]));
        }
    }
}

__global__ void __launch_bounds__(256,1) attn_kernel(
    const float* __restrict__ xyz,
    const float* __restrict__ d1_w, const float* __restrict__ d1_b,
    const float* __restrict__ d2_w, const float* __restrict__ d2_b,
    const float* __restrict__ sim_w, const float* __restrict__ sim_b,
    const float* __restrict__ g1_w, const float* __restrict__ g1_b,
    const float* __restrict__ g2_w, const float* __restrict__ g2_b,
    float* __restrict__ attn_out)
{
    extern __shared__ float smf[];
    float* sAT  = smf;                          // [128][132] transposed input
    float* sW   = sAT + DM*SAT_STRIDE;          // [128][128] weights
    float* sPE  = sW + DM*DM;                   // [128][128] pos_enc
    float* sSim = sPE + DM*DM;                  // [128]
    float* sKKd = sSim + 128;                   // [128] k·k dots
    float* sKxyz = sKKd + 128;                  // [128*3]
    float* sQxyz = sKxyz + 384;                 // [8*3]
    __shared__ int sIdx[128];

    const int t = threadIdx.x;
    const int ty = t >> 4, tx = t & 15;
    const int tile = blockIdx.x;                // 2048 tiles
    const int b = tile >> 9;                    // 512 tiles per batch
    const int n0 = (tile & 511) * TS;
    const int bn0 = b*Nn + n0;

    if (t < 128) {
        int id = g_knn[(size_t)bn0*KK + t];
        sIdx[t] = id;
        const float* p = xyz + (size_t)(b*Nn + id)*3;
        sKxyz[t*3+0]=p[0]; sKxyz[t*3+1]=p[1]; sKxyz[t*3+2]=p[2];
    } else if (t < 136) {
        int r = t - 128;
        const float* p = xyz + (size_t)(bn0 + r)*3;
        sQxyz[r*3+0]=p[0]; sQxyz[r*3+1]=p[1]; sQxyz[r*3+2]=p[2];
    }
    __syncthreads();

    // ---- stage A: h1 = relu(rel_pos @ d1 + b1) -> sAT ; stage weights d2_w -> sW
    #pragma unroll 4
    for (int i=0;i<64;i++) {
        int e = i*256 + t;
        int ch = e >> 7, pr = e & 127;
        int r = pr >> 4;
        float rx = sQxyz[r*3+0]-sKxyz[pr*3+0];
        float ry = sQxyz[r*3+1]-sKxyz[pr*3+1];
        float rz = sQxyz[r*3+2]-sKxyz[pr*3+2];
        float h = d1_b[ch];
        h = fmaf(rx, d1_w[ch], h);
        h = fmaf(ry, d1_w[DM+ch], h);
        h = fmaf(rz, d1_w[2*DM+ch], h);
        sAT[ch*SAT_STRIDE + pr] = fmaxf(h, 0.f);
    }
    for (int i = t*4; i < DM*DM; i += 1024)
        *(float4*)(sW+i) = *(const float4*)(d2_w+i);
    __syncthreads();

    unsigned long long acc[8][4];
    // ---- GEMM1: pos_enc = h1 @ d2_w
    #pragma unroll
    for (int i=0;i<8;i++)
        #pragma unroll
        for (int j=0;j<4;j++) acc[i][j]=0ull;
    gemm_tile2(sAT, sW, acc, ty, tx);

    // epilogue 1: pos_enc -> sPE ; ve = v_gather + pos_enc -> global
    #pragma unroll
    for (int i=0;i<8;i++) {
        int row = ty*8+i;
        float pv[8];
        #pragma unroll
        for (int j=0;j<4;j++) {
            float2 p = unpk(acc[i][j]);
            pv[2*j]   = p.x + d2_b[tx*8+2*j];
            pv[2*j+1] = p.y + d2_b[tx*8+2*j+1];
            sPE[row*DM + tx*8 + 2*j]   = pv[2*j];
            sPE[row*DM + tx*8 + 2*j+1] = pv[2*j+1];
        }
        const float* vp = g_v + (size_t)(b*Nn + sIdx[row])*DM + tx*8;
        float* vep = g_ve + ((size_t)(bn0*KK + row))*DM + tx*8;
        float4 va = *(const float4*)vp;
        float4 vb = *(const float4*)(vp+4);
        float4 oa = make_float4(va.x+pv[0], va.y+pv[1], va.z+pv[2], va.w+pv[3]);
        float4 ob = make_float4(vb.x+pv[4], vb.y+pv[5], vb.z+pv[6], vb.w+pv[7]);
        *(float4*)vep = oa; *(float4*)(vep+4) = ob;
    }
    __syncthreads();

    // ---- stage C: dots, q-k -> sAT, sim_w rows 1.. -> sW
    float qkdot = 0.f;
    if (t < 128) {
        const float4* qp = (const float4*)(g_q + (size_t)(bn0 + (t>>4))*DM);
        const float4* kp = (const float4*)(g_k + (size_t)(b*Nn + sIdx[t])*DM);
        #pragma unroll 8
        for (int c=0;c<32;c++) {
            float4 a = qp[c], k4 = kp[c];
            qkdot = fmaf(a.x,k4.x,qkdot); qkdot = fmaf(a.y,k4.y,qkdot);
            qkdot = fmaf(a.z,k4.z,qkdot); qkdot = fmaf(a.w,k4.w,qkdot);
        }
    } else {
        int p = t-128;
        const float4* kp = (const float4*)(g_k + (size_t)(b*Nn + sIdx[p])*DM);
        float s = 0.f;
        #pragma unroll 8
        for (int c=0;c<32;c++) {
            float4 k4 = kp[c];
            s = fmaf(k4.x,k4.x,s); s = fmaf(k4.y,k4.y,s);
            s = fmaf(k4.z,k4.z,s); s = fmaf(k4.w,k4.w,s);
        }
        sKKd[p] = s;
    }
    #pragma unroll 4
    for (int i=0;i<64;i++) {
        int e = i*256 + t;
        int ch = e >> 7, pr = e & 127;
        float qv = g_q[(size_t)(bn0 + (pr>>4))*DM + ch];
        float kv = g_k[(size_t)(b*Nn + sIdx[pr])*DM + ch];
        sAT[ch*SAT_STRIDE + pr] = qv - kv;
    }
    for (int i = t*4; i < DM*DM; i += 1024)
        *(float4*)(sW+i) = *(const float4*)(sim_w + DM + i);
    __syncthreads();
    if (t < 128) {
        float kn = fmaxf(sqrtf(sKKd[t]), EPSV);
        float qn = g_qn[bn0 + (t>>4)];
        sSim[t] = qkdot / (qn * kn);
    }
    __syncthreads();

    // ---- GEMM2: (q-k) @ sim_w[1:]
    #pragma unroll
    for (int i=0;i<8;i++)
        #pragma unroll
        for (int j=0;j<4;j++) acc[i][j]=0ull;
    gemm_tile2(sAT, sW, acc, ty, tx);
    __syncthreads();

    // epilogue 2: t = rel_qk + pos_enc -> sAT (transposed) ; g1_w -> sW
    #pragma unroll
    for (int i=0;i<8;i++) {
        int row = ty*8+i;
        float sv = sSim[row];
        #pragma unroll
        for (int j=0;j<4;j++) {
            float2 p = unpk(acc[i][j]);
            int col0 = tx*8+2*j;
            float tv0 = p.x + sv*sim_w[col0]   + sim_b[col0]   + sPE[row*DM + col0];
            float tv1 = p.y + sv*sim_w[col0+1] + sim_b[col0+1] + sPE[row*DM + col0+1];
            sAT[col0*SAT_STRIDE + row]     = tv0;
            sAT[(col0+1)*SAT_STRIDE + row] = tv1;
        }
    }
    for (int i = t*4; i < DM*DM; i += 1024)
        *(float4*)(sW+i) = *(const float4*)(g1_w+i);
    __syncthreads();

    // ---- GEMM3: a1 = relu(t @ g1 + b)
    #pragma unroll
    for (int i=0;i<8;i++)
        #pragma unroll
        for (int j=0;j<4;j++) acc[i][j]=0ull;
    gemm_tile2(sAT, sW, acc, ty, tx);
    __syncthreads();

    #pragma unroll
    for (int i=0;i<8;i++) {
        int row = ty*8+i;
        #pragma unroll
        for (int j=0;j<4;j++) {
            float2 p = unpk(acc[i][j]);
            int col0 = tx*8+2*j;
            sAT[col0*SAT_STRIDE + row]     = fmaxf(p.x + g1_b[col0],   0.f);
            sAT[(col0+1)*SAT_STRIDE + row] = fmaxf(p.y + g1_b[col0+1], 0.f);
        }
    }
    for (int i = t*4; i < DM*DM; i += 1024)
        *(float4*)(sW+i) = *(const float4*)(g2_w+i);
    __syncthreads();

    // ---- GEMM4: attn_pre = a1 @ g2 + b -> d_out attn region
    #pragma unroll
    for (int i=0;i<8;i++)
        #pragma unroll
        for (int j=0;j<4;j++) acc[i][j]=0ull;
    gemm_tile2(sAT, sW, acc, ty, tx);

    #pragma unroll
    for (int i=0;i<8;i++) {
        int row = ty*8+i;
        float* op = attn_out + ((size_t)(bn0*KK + row))*DM + tx*8;
        float o[8];
        #pragma unroll
        for (int j=0;j<4;j++) {
            float2 p = unpk(acc[i][j]);
            o[2*j]   = p.x + g2_b[tx*8+2*j];
            o[2*j+1] = p.y + g2_b[tx*8+2*j+1];
        }
        *(float4*)op     = make_float4(o[0],o[1],o[2],o[3]);
        *(float4*)(op+4) = make_float4(o[4],o[5],o[6],o[7]);
    }
}

// ---------------- softmax over K axis + weighted reduce ----------------
__global__ void softmax_kernel(float* __restrict__ attn) {
    int gid = blockIdx.x*blockDim.x + threadIdx.x;   // BN*DM threads
    int bn = gid >> 7, ch = gid & 127;
    size_t base = (size_t)bn*KK*DM + ch;
    const float sc = 0.08838834764831843f;           // 1/sqrt(128)
    float v[KK];
    float m = -3.4e38f;
    #pragma unroll
    for (int k=0;k<KK;k++){ v[k] = attn[base + k*DM]*sc; m = fmaxf(m, v[k]); }
    float s = 0.f;
    #pragma unroll
    for (int k=0;k<KK;k++){ v[k] = expf(v[k]-m); s += v[k]; }
    float inv = 1.0f/s;
    float r = 0.f;
    #pragma unroll
    for (int k=0;k<KK;k++){
        float a = v[k]*inv;
        attn[base + k*DM] = a;
        r = fmaf(a, g_ve[base + k*DM], r);
    }
    g_r[gid] = r;
}

// ---------------- res = r @ fc2 + b + features ----------------
__global__ void out_kernel(const float* __restrict__ fc2_w, const float* __restrict__ fc2_b,
                           const float* __restrict__ feat, float* __restrict__ res) {
    int gid = blockIdx.x*blockDim.x + threadIdx.x;   // BN*DP threads
    int bn = gid >> 6, c = gid & 63;
    const float* r = g_r + (size_t)bn*DM;
    float a = 0.f;
    #pragma unroll 8
    for (int d=0; d<DM; d++) a = fmaf(r[d], fc2_w[d*DP + c], a);
    res[gid] = a + fc2_b[c] + feat[gid];
}

// ---------------- launch ----------------
extern "C" void kernel_launch(void* const* d_in, const int* in_sizes, int n_in,
                              void* d_out, int out_size) {
    const float* xyz      = (const float*)d_in[0];
    const float* features = (const float*)d_in[1];
    const float* fc1_w = (const float*)d_in[2];
    const float* fc1_b = (const float*)d_in[3];
    const float* fc2_w = (const float*)d_in[4];
    const float* fc2_b = (const float*)d_in[5];
    const float* d1_w  = (const float*)d_in[6];
    const float* d1_b  = (const float*)d_in[7];
    const float* d2_w  = (const float*)d_in[8];
    const float* d2_b  = (const float*)d_in[9];
    const float* g1_w  = (const float*)d_in[10];
    const float* g1_b  = (const float*)d_in[11];
    const float* g2_w  = (const float*)d_in[12];
    const float* g2_b  = (const float*)d_in[13];
    const float* wq_w  = (const float*)d_in[14];
    const float* wk_w  = (const float*)d_in[15];
    const float* wv_w  = (const float*)d_in[16];
    const float* sim_w = (const float*)d_in[17];
    const float* sim_b = (const float*)d_in[18];

    float* res  = (float*)d_out;                       // (B,N,DP)
    float* attn = res + (size_t)BN*DP;                 // (B,N,K,DM)

    const int KNN_SMEM  = 4*Nn*(int)sizeof(float);     // 64 KB
    const int ATTN_SMEM = (DM*SAT_STRIDE + 2*DM*DM + 128 + 128 + 384 + 24)
                          * (int)sizeof(float);        // ~197 KB
    static int attr_done = 0;
    if (!attr_done) {
        cudaFuncSetAttribute(knn_kernel,  cudaFuncAttributeMaxDynamicSharedMemorySize, KNN_SMEM);
        cudaFuncSetAttribute(attn_kernel, cudaFuncAttributeMaxDynamicSharedMemorySize, ATTN_SMEM);
        attr_done = 1;
    }

    knn_kernel<<<dim3(Nn/256, Bb), 256, KNN_SMEM>>>(xyz);
    fc1_kernel<<<(BN*DM)/256, 256>>>(features, fc1_w, fc1_b);
    qkv_kernel<<<(BN*DM)/256, 256>>>(wq_w, wk_w, wv_w);
    qn_kernel<<<BN/8, 256>>>();
    attn_kernel<<<BN/TS, 256, ATTN_SMEM>>>(xyz, d1_w, d1_b, d2_w, d2_b,
                                           sim_w, sim_b, g1_w, g1_b, g2_w, g2_b, attn);
    softmax_kernel<<<(BN*DM)/256, 256>>>(attn);
    out_kernel<<<(BN*DP)/256, 256>>>(fc2_w, fc2_b, features, res);
}